// round 3
// baseline (speedup 1.0000x reference)
#include <cuda_runtime.h>
#include <cuda_bf16.h>
#include <math.h>

// ---------------------------------------------------------------------------
// ViT forward (DeiT-like): B=64, tokens N=198, E=768, 12 layers, heads=12, d=64
// Round 3: fp32 SGEMM (double-buffered, fused epilogues), smem attention
// (smem-broadcast AV instead of shfl). Architecture held pending first bench.
// ---------------------------------------------------------------------------

#define EMBED   768
#define DEPTH   12
#define HEADS   12
#define HEAD_DIM 64
#define HIDDEN  3072
#define BATCH   64
#define NTOK    198
#define NPATCH  196
#define ROWS    (BATCH * NTOK)      // 12672
#define PROWS   (BATCH * NPATCH)    // 12544
#define LN_EPS  1e-5f
#define ATT_SCALE 0.125f            // 64^-0.5

// ------------------------------- scratch -----------------------------------
__device__ float g_h[ROWS * EMBED];          // activations x (residual stream)
__device__ float g_y[ROWS * EMBED];          // LN output
__device__ float g_qkv[ROWS * 3 * EMBED];    // qkv (also reused as im2col patches)
__device__ float g_o[ROWS * EMBED];          // attention output
__device__ float g_hid[ROWS * HIDDEN];       // MLP hidden
__device__ float g_tmp[ROWS * EMBED];        // patch GEMM output
__device__ float g_wT[EMBED * EMBED];        // transposed conv weight

// ------------------------------- SGEMM -------------------------------------
// C[M,N] = epilogue(A[M,K] @ B[K,N]); M,N multiples of 128, K multiple of 8.
// MODE 0: C = AB
// MODE 1: C += AB + bias[n]          (residual accumulate, C preloaded)
// MODE 2: C = gelu(AB + bias[n])     (exact erf gelu)
#define BM 128
#define BN 128
#define BKK 8
#define TM 8
#define TN 8

template <int MODE>
__global__ __launch_bounds__(256, 2)
void sgemm_kernel(const float* __restrict__ A, const float* __restrict__ Bm,
                  float* __restrict__ C, const float* __restrict__ bias,
                  int M, int N, int K) {
    __shared__ float As[2][BKK][BM];
    __shared__ float Bs[2][BKK][BN];

    const int tid = threadIdx.x;
    const int blockRow = blockIdx.y;
    const int blockCol = blockIdx.x;

    const int aRow = tid >> 1;            // 0..127
    const int aCol = (tid & 1) * 4;       // 0 or 4
    const int bRow = tid >> 5;            // 0..7
    const int bCol = (tid & 31) * 4;      // 0..124

    const float* Ablk = A + (size_t)blockRow * BM * K;
    const float* Bblk = Bm + (size_t)blockCol * BN;

    const int tRow = (tid >> 4) * TM;
    const int tCol = (tid & 15) * TN;

    float acc[TM][TN];
#pragma unroll
    for (int i = 0; i < TM; i++)
#pragma unroll
        for (int j = 0; j < TN; j++) acc[i][j] = 0.f;

    // stage tile 0
    {
        float4 a = *(const float4*)(Ablk + (size_t)aRow * K + aCol);
        As[0][aCol + 0][aRow] = a.x;
        As[0][aCol + 1][aRow] = a.y;
        As[0][aCol + 2][aRow] = a.z;
        As[0][aCol + 3][aRow] = a.w;
        float4 bv = *(const float4*)(Bblk + (size_t)bRow * N + bCol);
        *(float4*)&Bs[0][bRow][bCol] = bv;
    }
    __syncthreads();

    int buf = 0;
    for (int k0 = 0; k0 < K; k0 += BKK) {
        const int nxt = k0 + BKK;
        float4 an, bn;
        if (nxt < K) {
            an = *(const float4*)(Ablk + (size_t)aRow * K + nxt + aCol);
            bn = *(const float4*)(Bblk + (size_t)(nxt + bRow) * N + bCol);
        }

#pragma unroll
        for (int kk = 0; kk < BKK; kk++) {
            float ra[TM], rb[TN];
#pragma unroll
            for (int i = 0; i < TM; i++) ra[i] = As[buf][kk][tRow + i];
#pragma unroll
            for (int j = 0; j < TN; j++) rb[j] = Bs[buf][kk][tCol + j];
#pragma unroll
            for (int i = 0; i < TM; i++)
#pragma unroll
                for (int j = 0; j < TN; j++) acc[i][j] = fmaf(ra[i], rb[j], acc[i][j]);
        }

        if (nxt < K) {
            const int nb = buf ^ 1;
            As[nb][aCol + 0][aRow] = an.x;
            As[nb][aCol + 1][aRow] = an.y;
            As[nb][aCol + 2][aRow] = an.z;
            As[nb][aCol + 3][aRow] = an.w;
            *(float4*)&Bs[nb][bRow][bCol] = bn;
            __syncthreads();
            buf = nb;
        }
    }

    float* Cblk = C + (size_t)blockRow * BM * N + blockCol * BN;

    float breg[TN];
    if (MODE != 0) {
#pragma unroll
        for (int j = 0; j < TN; j++) breg[j] = __ldg(bias + blockCol * BN + tCol + j);
    }

#pragma unroll
    for (int i = 0; i < TM; i++) {
        float* crow = Cblk + (size_t)(tRow + i) * N + tCol;
#pragma unroll
        for (int j = 0; j < TN; j += 4) {
            float4 v = make_float4(acc[i][j], acc[i][j + 1], acc[i][j + 2], acc[i][j + 3]);
            if (MODE == 1) {
                float4 r = *(float4*)(crow + j);
                v.x += r.x + breg[j + 0];
                v.y += r.y + breg[j + 1];
                v.z += r.z + breg[j + 2];
                v.w += r.w + breg[j + 3];
            } else if (MODE == 2) {
                v.x += breg[j + 0];
                v.y += breg[j + 1];
                v.z += breg[j + 2];
                v.w += breg[j + 3];
                v.x = 0.5f * v.x * (1.f + erff(v.x * 0.70710678118654752f));
                v.y = 0.5f * v.y * (1.f + erff(v.y * 0.70710678118654752f));
                v.z = 0.5f * v.z * (1.f + erff(v.z * 0.70710678118654752f));
                v.w = 0.5f * v.w * (1.f + erff(v.w * 0.70710678118654752f));
            }
            *(float4*)(crow + j) = v;
        }
    }
}

// ------------------------------ LayerNorm ----------------------------------
__device__ __forceinline__ float block_reduce_sum(float val, float* shared) {
    int lane = threadIdx.x & 31, wid = threadIdx.x >> 5;
#pragma unroll
    for (int o = 16; o > 0; o >>= 1) val += __shfl_xor_sync(0xffffffffu, val, o);
    if (lane == 0) shared[wid] = val;
    __syncthreads();
    float r = (threadIdx.x < 8) ? shared[threadIdx.x] : 0.f;
    if (wid == 0) {
#pragma unroll
        for (int o = 4; o > 0; o >>= 1) r += __shfl_xor_sync(0xffu, r, o);
        if (lane == 0) shared[0] = r;
    }
    __syncthreads();
    float out = shared[0];
    __syncthreads();
    return out;
}

__global__ __launch_bounds__(256)
void layernorm_kernel(const float* __restrict__ in, float* __restrict__ out,
                      const float* __restrict__ w, const float* __restrict__ b) {
    const int row = blockIdx.x;
    const float* x = in + (size_t)row * EMBED;
    __shared__ float sx[EMBED];
    __shared__ float red[32];
    const int tid = threadIdx.x;

    float local = 0.f;
#pragma unroll
    for (int i = tid; i < EMBED; i += 256) { float v = x[i]; sx[i] = v; local += v; }
    float mu = block_reduce_sum(local, red) * (1.f / EMBED);

    float lv = 0.f;
#pragma unroll
    for (int i = tid; i < EMBED; i += 256) { float d = sx[i] - mu; lv += d * d; }
    float var = block_reduce_sum(lv, red) * (1.f / EMBED);
    float rstd = rsqrtf(var + LN_EPS);

    float* o = out + (size_t)row * EMBED;
#pragma unroll
    for (int i = tid; i < EMBED; i += 256)
        o[i] = (sx[i] - mu) * rstd * w[i] + b[i];
}

// ------------------------------ Attention ----------------------------------
// One block per (b, head). Q,K,V [198][64] staged in padded smem.
// Per-warp row softmax; AV uses smem-broadcast probabilities (no shfl chain).
#define APAD 65
#define NTOK_PAD 224   // 7*32, padded prob row length per warp

__global__ __launch_bounds__(256)
void attention_kernel(const float* __restrict__ qkv, float* __restrict__ o) {
    extern __shared__ float sm[];
    float* Q  = sm;                       // 198*65
    float* Kt = Q + NTOK * APAD;          // 198*65
    float* V  = Kt + NTOK * APAD;         // 198*65
    float* P  = V + NTOK * APAD;          // 8 warps * 224 probs

    const int bh = blockIdx.x;
    const int b = bh / HEADS, hh = bh % HEADS;
    const float* base = qkv + (size_t)b * NTOK * 3 * EMBED + hh * HEAD_DIM;
    const int tid = threadIdx.x;

    for (int idx = tid; idx < NTOK * HEAD_DIM; idx += 256) {
        int n = idx >> 6, d = idx & 63;
        const float* row = base + (size_t)n * (3 * EMBED) + d;
        Q[n * APAD + d]  = row[0] * ATT_SCALE;
        Kt[n * APAD + d] = row[EMBED];
        V[n * APAD + d]  = row[2 * EMBED];
    }
    __syncthreads();

    const int warp = tid >> 5, lane = tid & 31;
    float* Pw = P + warp * NTOK_PAD;

    for (int r = warp; r < NTOK; r += 8) {
        float s[7];
        float mx = -1e30f;
        const float* qr = &Q[r * APAD];
#pragma unroll
        for (int t = 0; t < 7; t++) {
            int j = t * 32 + lane;
            float acc;
            if (j < NTOK) {
                const float* kr = &Kt[j * APAD];
                acc = 0.f;
#pragma unroll
                for (int d = 0; d < HEAD_DIM; d++) acc = fmaf(qr[d], kr[d], acc);
            } else acc = -1e30f;
            s[t] = acc;
            mx = fmaxf(mx, acc);
        }
#pragma unroll
        for (int ofs = 16; ofs > 0; ofs >>= 1) mx = fmaxf(mx, __shfl_xor_sync(0xffffffffu, mx, ofs));

        float sum = 0.f;
#pragma unroll
        for (int t = 0; t < 7; t++) {
            int j = t * 32 + lane;
            float e = (j < NTOK) ? __expf(s[t] - mx) : 0.f;
            Pw[t * 32 + lane] = e;     // per-warp private region; warp-synchronous
            sum += e;
        }
#pragma unroll
        for (int ofs = 16; ofs > 0; ofs >>= 1) sum += __shfl_xor_sync(0xffffffffu, sum, ofs);
        float inv = 1.f / sum;
        __syncwarp();

        float o0 = 0.f, o1 = 0.f;
#pragma unroll 2
        for (int j = 0; j < NTOK; j++) {
            float p = Pw[j];                      // smem broadcast, conflict-free
            o0 = fmaf(p, V[j * APAD + lane], o0);
            o1 = fmaf(p, V[j * APAD + lane + 32], o1);
        }
        __syncwarp();

        float* orow = o + ((size_t)(b * NTOK + r)) * EMBED + hh * HEAD_DIM;
        orow[lane]      = o0 * inv;
        orow[lane + 32] = o1 * inv;
    }
}

// ----------------------------- patch embedding ------------------------------
__global__ void im2col_kernel(const float* __restrict__ x, float* __restrict__ P) {
    int i = blockIdx.x * 256 + threadIdx.x;
    if (i >= PROWS * EMBED) return;
    int k = i % EMBED, m = i / EMBED;
    int b = m / NPATCH, p = m % NPATCH;
    int py = p / 14, px = p % 14;
    int ci = k >> 8, rem = k & 255, ky = rem >> 4, kx = rem & 15;
    P[i] = x[((size_t)(b * 3 + ci) * 224 + py * 16 + ky) * 224 + px * 16 + kx];
}

__global__ void transpose_w_kernel(const float* __restrict__ w, float* __restrict__ wT) {
    int i = blockIdx.x * 256 + threadIdx.x;
    if (i >= EMBED * EMBED) return;
    int n = i / EMBED, k = i % EMBED;
    wT[k * EMBED + n] = w[i];
}

__global__ void patch_epilogue_kernel(const float* __restrict__ t, float* __restrict__ h,
                                      const float* __restrict__ conv_b,
                                      const float* __restrict__ pos) {
    int i = blockIdx.x * 256 + threadIdx.x;
    if (i >= PROWS * EMBED) return;
    int c = i % EMBED, m = i / EMBED;
    int b = m / NPATCH, p = m % NPATCH;
    h[((size_t)(b * NTOK + 2 + p)) * EMBED + c] = t[i] + conv_b[c] + pos[p * EMBED + c];
}

__global__ void token_fill_kernel(float* __restrict__ h, const float* __restrict__ local_tok,
                                  const float* __restrict__ cls_tok) {
    int i = blockIdx.x * 256 + threadIdx.x;
    if (i >= BATCH * EMBED) return;
    int b = i / EMBED, c = i % EMBED;
    h[((size_t)(b * NTOK + 0)) * EMBED + c] = local_tok[c];
    h[((size_t)(b * NTOK + 1)) * EMBED + c] = cls_tok[c];
}

// ------------------------------- launcher -----------------------------------
template <int MODE>
static inline void run_gemm(const float* A, const float* B, float* C,
                            const float* bias, int M, int N, int K) {
    dim3 grid(N / BN, M / BM);
    sgemm_kernel<MODE><<<grid, 256>>>(A, B, C, bias, M, N, K);
}

extern "C" void kernel_launch(void* const* d_in, const int* in_sizes, int n_in,
                              void* d_out, int out_size) {
    const float* x          = (const float*)d_in[0];
    const float* conv_w     = (const float*)d_in[1];
    const float* conv_b     = (const float*)d_in[2];
    const float* pos_embed  = (const float*)d_in[3];
    const float* cls_token  = (const float*)d_in[4];
    const float* local_tok  = (const float*)d_in[5];
    const float* ln1_w      = (const float*)d_in[6];
    const float* ln1_b      = (const float*)d_in[7];
    const float* qkv_w      = (const float*)d_in[8];
    const float* proj_w     = (const float*)d_in[9];
    const float* proj_b     = (const float*)d_in[10];
    const float* ln2_w      = (const float*)d_in[11];
    const float* ln2_b      = (const float*)d_in[12];
    const float* fc1_w      = (const float*)d_in[13];
    const float* fc1_b      = (const float*)d_in[14];
    const float* fc2_w      = (const float*)d_in[15];
    const float* fc2_b      = (const float*)d_in[16];
    const float* lnf_w      = (const float*)d_in[17];
    const float* lnf_b      = (const float*)d_in[18];
    float* out = (float*)d_out;

    float *h_, *y_, *qkv_, *o_, *hid_, *tmp_, *wT_;
    cudaGetSymbolAddress((void**)&h_,   g_h);
    cudaGetSymbolAddress((void**)&y_,   g_y);
    cudaGetSymbolAddress((void**)&qkv_, g_qkv);
    cudaGetSymbolAddress((void**)&o_,   g_o);
    cudaGetSymbolAddress((void**)&hid_, g_hid);
    cudaGetSymbolAddress((void**)&tmp_, g_tmp);
    cudaGetSymbolAddress((void**)&wT_,  g_wT);

    // attention smem: Q,K,V padded + per-warp prob scratch (~161 KB)
    const int att_smem = (3 * NTOK * APAD + 8 * NTOK_PAD) * (int)sizeof(float);
    cudaFuncSetAttribute(attention_kernel, cudaFuncAttributeMaxDynamicSharedMemorySize, att_smem);

    // ---- patch embed ----
    {
        int total = PROWS * EMBED;
        im2col_kernel<<<(total + 255) / 256, 256>>>(x, qkv_);
        transpose_w_kernel<<<(EMBED * EMBED + 255) / 256, 256>>>(conv_w, wT_);
        run_gemm<0>(qkv_, wT_, tmp_, nullptr, PROWS, EMBED, EMBED);
        patch_epilogue_kernel<<<(total + 255) / 256, 256>>>(tmp_, h_, conv_b, pos_embed);
        token_fill_kernel<<<(BATCH * EMBED + 255) / 256, 256>>>(h_, local_tok, cls_token);
    }

    // ---- transformer blocks ----
    for (int l = 0; l < DEPTH; l++) {
        const float* l1w = ln1_w + (size_t)l * EMBED;
        const float* l1b = ln1_b + (size_t)l * EMBED;
        const float* qw  = qkv_w + (size_t)l * EMBED * 3 * EMBED;
        const float* pw  = proj_w + (size_t)l * EMBED * EMBED;
        const float* pb  = proj_b + (size_t)l * EMBED;
        const float* l2w = ln2_w + (size_t)l * EMBED;
        const float* l2b = ln2_b + (size_t)l * EMBED;
        const float* f1w = fc1_w + (size_t)l * EMBED * HIDDEN;
        const float* f1b = fc1_b + (size_t)l * HIDDEN;
        const float* f2w = fc2_w + (size_t)l * HIDDEN * EMBED;
        const float* f2b = fc2_b + (size_t)l * EMBED;

        // attention
        layernorm_kernel<<<ROWS, 256>>>(h_, y_, l1w, l1b);
        run_gemm<0>(y_, qw, qkv_, nullptr, ROWS, 3 * EMBED, EMBED);
        attention_kernel<<<BATCH * HEADS, 256, att_smem>>>(qkv_, o_);
        run_gemm<1>(o_, pw, h_, pb, ROWS, EMBED, EMBED);   // h += o@pw + pb

        // MLP
        layernorm_kernel<<<ROWS, 256>>>(h_, y_, l2w, l2b);
        run_gemm<2>(y_, f1w, hid_, f1b, ROWS, HIDDEN, EMBED);  // hid = gelu(y@f1w + f1b)
        run_gemm<1>(hid_, f2w, h_, f2b, ROWS, EMBED, HIDDEN);  // h += hid@f2w + f2b
    }

    // ---- final LN -> d_out ----
    layernorm_kernel<<<ROWS, 256>>>(h_, out, lnf_w, lnf_b);
}

// round 4
// speedup vs baseline: 1.3069x; 1.3069x over previous
#include <cuda_runtime.h>
#include <cuda_bf16.h>
#include <mma.h>
#include <math.h>

using namespace nvcuda;

// ---------------------------------------------------------------------------
// ViT forward (DeiT-like): B=64, tokens N=198, E=768, 12 layers, heads=12, d=64
// Round 4: TF32 tensor-core GEMM (WMMA m16n16k8, double-buffered smem, fused
// epilogues via smem staging). Attention / LN unchanged from round 3.
// ---------------------------------------------------------------------------

#define EMBED   768
#define DEPTH   12
#define HEADS   12
#define HEAD_DIM 64
#define HIDDEN  3072
#define BATCH   64
#define NTOK    198
#define NPATCH  196
#define ROWS    (BATCH * NTOK)      // 12672 = 99*128
#define PROWS   (BATCH * NPATCH)    // 12544 = 98*128
#define LN_EPS  1e-5f
#define ATT_SCALE 0.125f            // 64^-0.5

// ------------------------------- scratch -----------------------------------
__device__ float g_h[ROWS * EMBED];          // activations x (residual stream)
__device__ float g_y[ROWS * EMBED];          // LN output
__device__ float g_qkv[ROWS * 3 * EMBED];    // qkv (also reused as im2col patches)
__device__ float g_o[ROWS * EMBED];          // attention output
__device__ float g_hid[ROWS * HIDDEN];       // MLP hidden
__device__ float g_tmp[ROWS * EMBED];        // patch GEMM output
__device__ float g_wT[EMBED * EMBED];        // transposed conv weight

// --------------------------- TF32 WMMA GEMM --------------------------------
// C[M,N] = epilogue(A[M,K] @ B[K,N]); M,N multiples of 128, K multiple of 32.
// MODE 0: C = AB
// MODE 1: C += AB + bias[n]          (residual accumulate, C preloaded)
// MODE 2: C = gelu(AB + bias[n])     (exact erf gelu)
#define WBM 128
#define WBN 128
#define WBK 32
#define LDA_S 36            // WBK + 4 pad (floats)
#define LDB_S 132           // WBN + 4 pad (floats)
#define A_TILE_F (WBM * LDA_S)   // 4608 floats
#define B_TILE_F (WBK * LDB_S)   // 4224 floats
#define GEMM_SMEM_F (2 * A_TILE_F + 2 * B_TILE_F)  // 17664 floats = 70656 B

template <int MODE>
__global__ __launch_bounds__(256, 2)
void wgemm_kernel(const float* __restrict__ A, const float* __restrict__ Bm,
                  float* __restrict__ C, const float* __restrict__ bias,
                  int M, int N, int K) {
    extern __shared__ float sm[];
    float* As = sm;                       // [2][A_TILE_F]
    float* Bs = sm + 2 * A_TILE_F;        // [2][B_TILE_F]
    float* Epi = sm;                      // union, used after mainloop

    const int tid  = threadIdx.x;
    const int warp = tid >> 5;
    const int lane = tid & 31;
    const int warpM = warp >> 1;          // 0..3 -> 32-row slab
    const int warpN = warp & 1;           // 0..1 -> 64-col slab

    const int blockRow = blockIdx.y;
    const int blockCol = blockIdx.x;

    const float* Ablk = A + (size_t)blockRow * WBM * K;
    const float* Bblk = Bm + (size_t)blockCol * WBN;

    wmma::fragment<wmma::accumulator, 16, 16, 8, float> acc[2][4];
#pragma unroll
    for (int i = 0; i < 2; i++)
#pragma unroll
        for (int j = 0; j < 4; j++) wmma::fill_fragment(acc[i][j], 0.f);

    // global->smem staging helpers (tf32 conversion at smem store)
    // A: 1024 float4 loads; idx -> row=idx>>3, c4=idx&7
    // B: 1024 float4 loads; idx -> row=idx>>5, c4=idx&31
    auto stageA = [&](int buf, float4 v, int idx) {
        int row = idx >> 3, c = (idx & 7) * 4;
        float* d = As + buf * A_TILE_F + row * LDA_S + c;
        d[0] = wmma::__float_to_tf32(v.x);
        d[1] = wmma::__float_to_tf32(v.y);
        d[2] = wmma::__float_to_tf32(v.z);
        d[3] = wmma::__float_to_tf32(v.w);
    };
    auto stageB = [&](int buf, float4 v, int idx) {
        int row = idx >> 5, c = (idx & 31) * 4;
        float* d = Bs + buf * B_TILE_F + row * LDB_S + c;
        d[0] = wmma::__float_to_tf32(v.x);
        d[1] = wmma::__float_to_tf32(v.y);
        d[2] = wmma::__float_to_tf32(v.z);
        d[3] = wmma::__float_to_tf32(v.w);
    };

    // stage tile 0
#pragma unroll
    for (int i = 0; i < 4; i++) {
        int idx = tid + i * 256;
        int arow = idx >> 3, ac = (idx & 7) * 4;
        stageA(0, *(const float4*)(Ablk + (size_t)arow * K + ac), idx);
        int brow = idx >> 5, bc = (idx & 31) * 4;
        stageB(0, *(const float4*)(Bblk + (size_t)brow * N + bc), idx);
    }
    __syncthreads();

    int buf = 0;
    for (int k0 = 0; k0 < K; k0 += WBK) {
        const int nxt = k0 + WBK;
        float4 pa[4], pb[4];
        if (nxt < K) {
#pragma unroll
            for (int i = 0; i < 4; i++) {
                int idx = tid + i * 256;
                int arow = idx >> 3, ac = (idx & 7) * 4;
                pa[i] = *(const float4*)(Ablk + (size_t)arow * K + nxt + ac);
                int brow = idx >> 5, bc = (idx & 31) * 4;
                pb[i] = *(const float4*)(Bblk + (size_t)(nxt + brow) * N + bc);
            }
        }

        const float* Ab = As + buf * A_TILE_F;
        const float* Bb = Bs + buf * B_TILE_F;
#pragma unroll
        for (int ks = 0; ks < 4; ks++) {
            wmma::fragment<wmma::matrix_a, 16, 16, 8, wmma::precision::tf32, wmma::row_major> af[2];
            wmma::fragment<wmma::matrix_b, 16, 16, 8, wmma::precision::tf32, wmma::row_major> bf[4];
#pragma unroll
            for (int i = 0; i < 2; i++)
                wmma::load_matrix_sync(af[i], Ab + (warpM * 32 + i * 16) * LDA_S + ks * 8, LDA_S);
#pragma unroll
            for (int j = 0; j < 4; j++)
                wmma::load_matrix_sync(bf[j], Bb + (ks * 8) * LDB_S + warpN * 64 + j * 16, LDB_S);
#pragma unroll
            for (int i = 0; i < 2; i++)
#pragma unroll
                for (int j = 0; j < 4; j++)
                    wmma::mma_sync(acc[i][j], af[i], bf[j], acc[i][j]);
        }

        if (nxt < K) {
            const int nb = buf ^ 1;
#pragma unroll
            for (int i = 0; i < 4; i++) {
                int idx = tid + i * 256;
                stageA(nb, pa[i], idx);
                stageB(nb, pb[i], idx);
            }
            __syncthreads();
            buf = nb;
        }
    }

    // ---- epilogue: stage per-warp 32x64 region in smem, then fused store ----
    __syncthreads();   // everyone done reading As/Bs before union reuse
    float* ep = Epi + warp * (32 * 64);
#pragma unroll
    for (int i = 0; i < 2; i++)
#pragma unroll
        for (int j = 0; j < 4; j++)
            wmma::store_matrix_sync(ep + (i * 16) * 64 + j * 16, acc[i][j], 64, wmma::mem_row_major);
    __syncwarp();

    const int gr0 = blockRow * WBM + warpM * 32;
    const int gc0 = blockCol * WBN + warpN * 64;
#pragma unroll 4
    for (int e = 0; e < 64; e++) {
        int idx = e * 32 + lane;
        int r = idx >> 6, c = idx & 63;
        float v = ep[r * 64 + c];
        float* cptr = C + (size_t)(gr0 + r) * N + gc0 + c;
        if (MODE == 1) {
            v += *cptr + __ldg(bias + gc0 + c);
        } else if (MODE == 2) {
            v += __ldg(bias + gc0 + c);
            v = 0.5f * v * (1.f + erff(v * 0.70710678118654752f));
        }
        *cptr = v;
    }
}

// ------------------------------ LayerNorm ----------------------------------
__device__ __forceinline__ float block_reduce_sum(float val, float* shared) {
    int lane = threadIdx.x & 31, wid = threadIdx.x >> 5;
#pragma unroll
    for (int o = 16; o > 0; o >>= 1) val += __shfl_xor_sync(0xffffffffu, val, o);
    if (lane == 0) shared[wid] = val;
    __syncthreads();
    float r = (threadIdx.x < 8) ? shared[threadIdx.x] : 0.f;
    if (wid == 0) {
#pragma unroll
        for (int o = 4; o > 0; o >>= 1) r += __shfl_xor_sync(0xffu, r, o);
        if (lane == 0) shared[0] = r;
    }
    __syncthreads();
    float out = shared[0];
    __syncthreads();
    return out;
}

__global__ __launch_bounds__(256)
void layernorm_kernel(const float* __restrict__ in, float* __restrict__ out,
                      const float* __restrict__ w, const float* __restrict__ b) {
    const int row = blockIdx.x;
    const float* x = in + (size_t)row * EMBED;
    __shared__ float sx[EMBED];
    __shared__ float red[32];
    const int tid = threadIdx.x;

    float local = 0.f;
#pragma unroll
    for (int i = tid; i < EMBED; i += 256) { float v = x[i]; sx[i] = v; local += v; }
    float mu = block_reduce_sum(local, red) * (1.f / EMBED);

    float lv = 0.f;
#pragma unroll
    for (int i = tid; i < EMBED; i += 256) { float d = sx[i] - mu; lv += d * d; }
    float var = block_reduce_sum(lv, red) * (1.f / EMBED);
    float rstd = rsqrtf(var + LN_EPS);

    float* o = out + (size_t)row * EMBED;
#pragma unroll
    for (int i = tid; i < EMBED; i += 256)
        o[i] = (sx[i] - mu) * rstd * w[i] + b[i];
}

// ------------------------------ Attention ----------------------------------
// One block per (b, head). Q,K,V [198][64] staged in padded smem.
#define APAD 65
#define NTOK_PAD 224   // 7*32, padded prob row length per warp

__global__ __launch_bounds__(256)
void attention_kernel(const float* __restrict__ qkv, float* __restrict__ o) {
    extern __shared__ float sm[];
    float* Q  = sm;                       // 198*65
    float* Kt = Q + NTOK * APAD;          // 198*65
    float* V  = Kt + NTOK * APAD;         // 198*65
    float* P  = V + NTOK * APAD;          // 8 warps * 224 probs

    const int bh = blockIdx.x;
    const int b = bh / HEADS, hh = bh % HEADS;
    const float* base = qkv + (size_t)b * NTOK * 3 * EMBED + hh * HEAD_DIM;
    const int tid = threadIdx.x;

    for (int idx = tid; idx < NTOK * HEAD_DIM; idx += 256) {
        int n = idx >> 6, d = idx & 63;
        const float* row = base + (size_t)n * (3 * EMBED) + d;
        Q[n * APAD + d]  = row[0] * ATT_SCALE;
        Kt[n * APAD + d] = row[EMBED];
        V[n * APAD + d]  = row[2 * EMBED];
    }
    __syncthreads();

    const int warp = tid >> 5, lane = tid & 31;
    float* Pw = P + warp * NTOK_PAD;

    for (int r = warp; r < NTOK; r += 8) {
        float s[7];
        float mx = -1e30f;
        const float* qr = &Q[r * APAD];
#pragma unroll
        for (int t = 0; t < 7; t++) {
            int j = t * 32 + lane;
            float acc;
            if (j < NTOK) {
                const float* kr = &Kt[j * APAD];
                acc = 0.f;
#pragma unroll
                for (int d = 0; d < HEAD_DIM; d++) acc = fmaf(qr[d], kr[d], acc);
            } else acc = -1e30f;
            s[t] = acc;
            mx = fmaxf(mx, acc);
        }
#pragma unroll
        for (int ofs = 16; ofs > 0; ofs >>= 1) mx = fmaxf(mx, __shfl_xor_sync(0xffffffffu, mx, ofs));

        float sum = 0.f;
#pragma unroll
        for (int t = 0; t < 7; t++) {
            int j = t * 32 + lane;
            float e = (j < NTOK) ? __expf(s[t] - mx) : 0.f;
            Pw[t * 32 + lane] = e;     // per-warp private region; warp-synchronous
            sum += e;
        }
#pragma unroll
        for (int ofs = 16; ofs > 0; ofs >>= 1) sum += __shfl_xor_sync(0xffffffffu, sum, ofs);
        float inv = 1.f / sum;
        __syncwarp();

        float o0 = 0.f, o1 = 0.f;
#pragma unroll 2
        for (int j = 0; j < NTOK; j++) {
            float p = Pw[j];                      // smem broadcast, conflict-free
            o0 = fmaf(p, V[j * APAD + lane], o0);
            o1 = fmaf(p, V[j * APAD + lane + 32], o1);
        }
        __syncwarp();

        float* orow = o + ((size_t)(b * NTOK + r)) * EMBED + hh * HEAD_DIM;
        orow[lane]      = o0 * inv;
        orow[lane + 32] = o1 * inv;
    }
}

// ----------------------------- patch embedding ------------------------------
__global__ void im2col_kernel(const float* __restrict__ x, float* __restrict__ P) {
    int i = blockIdx.x * 256 + threadIdx.x;
    if (i >= PROWS * EMBED) return;
    int k = i % EMBED, m = i / EMBED;
    int b = m / NPATCH, p = m % NPATCH;
    int py = p / 14, px = p % 14;
    int ci = k >> 8, rem = k & 255, ky = rem >> 4, kx = rem & 15;
    P[i] = x[((size_t)(b * 3 + ci) * 224 + py * 16 + ky) * 224 + px * 16 + kx];
}

__global__ void transpose_w_kernel(const float* __restrict__ w, float* __restrict__ wT) {
    int i = blockIdx.x * 256 + threadIdx.x;
    if (i >= EMBED * EMBED) return;
    int n = i / EMBED, k = i % EMBED;
    wT[k * EMBED + n] = w[i];
}

__global__ void patch_epilogue_kernel(const float* __restrict__ t, float* __restrict__ h,
                                      const float* __restrict__ conv_b,
                                      const float* __restrict__ pos) {
    int i = blockIdx.x * 256 + threadIdx.x;
    if (i >= PROWS * EMBED) return;
    int c = i % EMBED, m = i / EMBED;
    int b = m / NPATCH, p = m % NPATCH;
    h[((size_t)(b * NTOK + 2 + p)) * EMBED + c] = t[i] + conv_b[c] + pos[p * EMBED + c];
}

__global__ void token_fill_kernel(float* __restrict__ h, const float* __restrict__ local_tok,
                                  const float* __restrict__ cls_tok) {
    int i = blockIdx.x * 256 + threadIdx.x;
    if (i >= BATCH * EMBED) return;
    int b = i / EMBED, c = i % EMBED;
    h[((size_t)(b * NTOK + 0)) * EMBED + c] = local_tok[c];
    h[((size_t)(b * NTOK + 1)) * EMBED + c] = cls_tok[c];
}

// ------------------------------- launcher -----------------------------------
#define GEMM_SMEM_B (GEMM_SMEM_F * (int)sizeof(float))

template <int MODE>
static inline void run_gemm(const float* A, const float* B, float* C,
                            const float* bias, int M, int N, int K) {
    dim3 grid(N / WBN, M / WBM);
    wgemm_kernel<MODE><<<grid, 256, GEMM_SMEM_B>>>(A, B, C, bias, M, N, K);
}

extern "C" void kernel_launch(void* const* d_in, const int* in_sizes, int n_in,
                              void* d_out, int out_size) {
    const float* x          = (const float*)d_in[0];
    const float* conv_w     = (const float*)d_in[1];
    const float* conv_b     = (const float*)d_in[2];
    const float* pos_embed  = (const float*)d_in[3];
    const float* cls_token  = (const float*)d_in[4];
    const float* local_tok  = (const float*)d_in[5];
    const float* ln1_w      = (const float*)d_in[6];
    const float* ln1_b      = (const float*)d_in[7];
    const float* qkv_w      = (const float*)d_in[8];
    const float* proj_w     = (const float*)d_in[9];
    const float* proj_b     = (const float*)d_in[10];
    const float* ln2_w      = (const float*)d_in[11];
    const float* ln2_b      = (const float*)d_in[12];
    const float* fc1_w      = (const float*)d_in[13];
    const float* fc1_b      = (const float*)d_in[14];
    const float* fc2_w      = (const float*)d_in[15];
    const float* fc2_b      = (const float*)d_in[16];
    const float* lnf_w      = (const float*)d_in[17];
    const float* lnf_b      = (const float*)d_in[18];
    float* out = (float*)d_out;

    float *h_, *y_, *qkv_, *o_, *hid_, *tmp_, *wT_;
    cudaGetSymbolAddress((void**)&h_,   g_h);
    cudaGetSymbolAddress((void**)&y_,   g_y);
    cudaGetSymbolAddress((void**)&qkv_, g_qkv);
    cudaGetSymbolAddress((void**)&o_,   g_o);
    cudaGetSymbolAddress((void**)&hid_, g_hid);
    cudaGetSymbolAddress((void**)&tmp_, g_tmp);
    cudaGetSymbolAddress((void**)&wT_,  g_wT);

    // opt-in smem sizes
    static int configured = 0;
    cudaFuncSetAttribute(wgemm_kernel<0>, cudaFuncAttributeMaxDynamicSharedMemorySize, GEMM_SMEM_B);
    cudaFuncSetAttribute(wgemm_kernel<1>, cudaFuncAttributeMaxDynamicSharedMemorySize, GEMM_SMEM_B);
    cudaFuncSetAttribute(wgemm_kernel<2>, cudaFuncAttributeMaxDynamicSharedMemorySize, GEMM_SMEM_B);
    const int att_smem = (3 * NTOK * APAD + 8 * NTOK_PAD) * (int)sizeof(float);
    cudaFuncSetAttribute(attention_kernel, cudaFuncAttributeMaxDynamicSharedMemorySize, att_smem);
    (void)configured;

    // ---- patch embed ----
    {
        int total = PROWS * EMBED;
        im2col_kernel<<<(total + 255) / 256, 256>>>(x, qkv_);
        transpose_w_kernel<<<(EMBED * EMBED + 255) / 256, 256>>>(conv_w, wT_);
        run_gemm<0>(qkv_, wT_, tmp_, nullptr, PROWS, EMBED, EMBED);
        patch_epilogue_kernel<<<(total + 255) / 256, 256>>>(tmp_, h_, conv_b, pos_embed);
        token_fill_kernel<<<(BATCH * EMBED + 255) / 256, 256>>>(h_, local_tok, cls_token);
    }

    // ---- transformer blocks ----
    for (int l = 0; l < DEPTH; l++) {
        const float* l1w = ln1_w + (size_t)l * EMBED;
        const float* l1b = ln1_b + (size_t)l * EMBED;
        const float* qw  = qkv_w + (size_t)l * EMBED * 3 * EMBED;
        const float* pw  = proj_w + (size_t)l * EMBED * EMBED;
        const float* pb  = proj_b + (size_t)l * EMBED;
        const float* l2w = ln2_w + (size_t)l * EMBED;
        const float* l2b = ln2_b + (size_t)l * EMBED;
        const float* f1w = fc1_w + (size_t)l * EMBED * HIDDEN;
        const float* f1b = fc1_b + (size_t)l * HIDDEN;
        const float* f2w = fc2_w + (size_t)l * HIDDEN * EMBED;
        const float* f2b = fc2_b + (size_t)l * EMBED;

        // attention
        layernorm_kernel<<<ROWS, 256>>>(h_, y_, l1w, l1b);
        run_gemm<0>(y_, qw, qkv_, nullptr, ROWS, 3 * EMBED, EMBED);
        attention_kernel<<<BATCH * HEADS, 256, att_smem>>>(qkv_, o_);
        run_gemm<1>(o_, pw, h_, pb, ROWS, EMBED, EMBED);   // h += o@pw + pb

        // MLP
        layernorm_kernel<<<ROWS, 256>>>(h_, y_, l2w, l2b);
        run_gemm<2>(y_, f1w, hid_, f1b, ROWS, HIDDEN, EMBED);  // hid = gelu(y@f1w + f1b)
        run_gemm<1>(hid_, f2w, h_, f2b, ROWS, EMBED, HIDDEN);  // h += hid@f2w + f2b
    }

    // ---- final LN -> d_out ----
    layernorm_kernel<<<ROWS, 256>>>(h_, out, lnf_w, lnf_b);
}